// round 4
// baseline (speedup 1.0000x reference)
#include <cuda_runtime.h>
#include <math.h>

// Problem constants
#define NN   256
#define CC   512
#define TT   4
#define HH   8
#define WWID 8
#define HWSZ 64          // HH*WWID
#define PP   256         // TT*HWSZ

typedef unsigned long long ull;

// ---------------------------------------------------------------------------
// Scratch (device globals — no allocation allowed).
// Layout for q/k/v/virt is position-major: [p][n][c], p = t*64 + h*8 + w.
// ---------------------------------------------------------------------------
__device__ __align__(16) float g_q[PP * NN * CC];
__device__ __align__(16) float g_k[PP * NN * CC];
__device__ __align__(16) float g_v[PP * NN * CC];
__device__ __align__(16) float g_virt[PP * NN * CC];
__device__ __align__(16) float g_att[PP * NN * NN];
__device__ float g_mu[NN];
__device__ float g_rs[NN];

// ---------------------------------------------------------------------------
// Packed f32x2 helpers (Blackwell FFMA2 path)
// ---------------------------------------------------------------------------
__device__ __forceinline__ ull pack2(float v) {
    ull r;
    asm("mov.b64 %0, {%1, %1};" : "=l"(r) : "f"(v));
    return r;
}
__device__ __forceinline__ ull fma2(ull a, ull b, ull c) {
    ull d;
    asm("fma.rn.f32x2 %0, %1, %2, %3;" : "=l"(d) : "l"(a), "l"(b), "l"(c));
    return d;
}
__device__ __forceinline__ void unpack2(ull a, float& lo, float& hi) {
    asm("mov.b64 {%0, %1}, %2;" : "=f"(lo), "=f"(hi) : "l"(a));
}

// ---------------------------------------------------------------------------
// K1: q,k,v = conv1x3x3(x, Wq/Wk/Wv).  One block = one (n,t) slice × 64 co.
// Thread map: lane -> co pair (2 channels, packed f32x2), warp -> h row,
// each thread covers all 8 w positions. x tile staged with halo in smem.
// Writes q/k/v in [p][n][c] layout (coalesced 256B per warp).
// ---------------------------------------------------------------------------
__global__ __launch_bounds__(256) void conv_qkv_kernel(
    const float* __restrict__ x,
    const float* __restrict__ Wq,
    const float* __restrict__ Wk,
    const float* __restrict__ Wv)
{
    __shared__ __align__(16) float ws[3 * 4 * 9 * 64];  // [conv][ci][s][co]  27.6 KB
    __shared__ __align__(16) float xs[4 * 10 * 10];     // [ci][h+halo][w+halo]

    const int co_base = blockIdx.x * 64;
    const int nt = blockIdx.y;
    const int n = nt >> 2, t = nt & 3;
    const int tid = threadIdx.x;
    const int l = tid & 31, wp = tid >> 5;   // wp = output h row

    ull acc[3][8];
#pragma unroll
    for (int c = 0; c < 3; c++)
#pragma unroll
        for (int i = 0; i < 8; i++) acc[c][i] = 0ULL;

    for (int kb = 0; kb < 128; kb++) {
        const int ci0 = kb * 4;
        // stage weights: [conv][ci][s][co]
        for (int idx = tid; idx < 6912; idx += 256) {
            int conv = idx / 2304; int r = idx - conv * 2304;
            int co = r / 36;       int r2 = r - co * 36;
            int ci = r2 / 9;       int s = r2 - ci * 9;
            const float* Wsrc = (conv == 0) ? Wq : ((conv == 1) ? Wk : Wv);
            ws[((conv * 4 + ci) * 9 + s) * 64 + co] =
                Wsrc[((co_base + co) * CC + ci0 + ci) * 9 + s];
        }
        // stage x tile with zero halo (padding (1,1) in h,w)
        for (int idx = tid; idx < 400; idx += 256) {
            int ci = idx / 100; int r = idx - ci * 100;
            int hh = r / 10;    int wwv = r - hh * 10;
            int hs = hh - 1, wsv = wwv - 1;
            float v = 0.0f;
            if ((unsigned)hs < 8u && (unsigned)wsv < 8u)
                v = x[((n * CC + ci0 + ci) * TT + t) * HWSZ + hs * 8 + wsv];
            xs[idx] = v;
        }
        __syncthreads();
#pragma unroll
        for (int ci = 0; ci < 4; ci++) {
#pragma unroll
            for (int dh = 0; dh < 3; dh++) {
                const float* row = &xs[(ci * 10 + wp + dh) * 10];
                ull xr2[10];
#pragma unroll
                for (int j = 0; j < 10; j++) xr2[j] = pack2(row[j]);
#pragma unroll
                for (int dw = 0; dw < 3; dw++) {
                    const int s = dh * 3 + dw;
#pragma unroll
                    for (int cv = 0; cv < 3; cv++) {
                        ull w2 = *(const ull*)&ws[((cv * 4 + ci) * 9 + s) * 64 + 2 * l];
#pragma unroll
                        for (int i = 0; i < 8; i++)
                            acc[cv][i] = fma2(w2, xr2[i + dw], acc[cv][i]);
                    }
                }
            }
        }
        __syncthreads();
    }
#pragma unroll
    for (int i = 0; i < 8; i++) {
        const int p = t * HWSZ + wp * 8 + i;
        const int off = (p * NN + n) * CC + co_base + 2 * l;
        *(ull*)&g_q[off] = acc[0][i];
        *(ull*)&g_k[off] = acc[1][i];
        *(ull*)&g_v[off] = acc[2][i];
    }
}

// ---------------------------------------------------------------------------
// K2: per-position scores  S_p = (Q_p K_p^T) * 1/sqrt(C).
// Block = 64 i-rows × 128 j-cols of one p.  Lane -> j pairs, warp -> i rows.
// ---------------------------------------------------------------------------
__global__ __launch_bounds__(256) void scores_kernel()
{
    __shared__ __align__(16) float qs[16 * 64];    // [kk][i]
    __shared__ __align__(16) float ks[16 * 128];   // [kk][j]
    const int p = blockIdx.y;
    const int jt = blockIdx.x & 1, it = blockIdx.x >> 1;
    const int tid = threadIdx.x, l = tid & 31, wp = tid >> 5;

    ull acc[8][2];
#pragma unroll
    for (int r = 0; r < 8; r++) { acc[r][0] = 0ULL; acc[r][1] = 0ULL; }

    for (int c0 = 0; c0 < CC; c0 += 16) {
        for (int idx = tid; idx < 1024; idx += 256) {
            int i_loc = idx >> 4, kk = idx & 15;
            qs[kk * 64 + i_loc] = g_q[(p * NN + it * 64 + i_loc) * CC + c0 + kk];
        }
        for (int idx = tid; idx < 2048; idx += 256) {
            int j_loc = idx >> 4, kk = idx & 15;
            ks[kk * 128 + j_loc] = g_k[(p * NN + jt * 128 + j_loc) * CC + c0 + kk];
        }
        __syncthreads();
#pragma unroll
        for (int kk = 0; kk < 16; kk++) {
            ull kA = *(const ull*)&ks[kk * 128 + 2 * l];
            ull kB = *(const ull*)&ks[kk * 128 + 64 + 2 * l];
#pragma unroll
            for (int r = 0; r < 8; r++) {
                ull qb = pack2(qs[kk * 64 + wp * 8 + r]);
                acc[r][0] = fma2(qb, kA, acc[r][0]);
                acc[r][1] = fma2(qb, kB, acc[r][1]);
            }
        }
        __syncthreads();
    }
    const float scale = rsqrtf((float)CC);
#pragma unroll
    for (int r = 0; r < 8; r++) {
#pragma unroll
        for (int hf = 0; hf < 2; hf++) {
            float lo, hi;
            unpack2(acc[r][hf], lo, hi);
            const int i = it * 64 + wp * 8 + r;
            const int j = jt * 128 + hf * 64 + 2 * l;
            float2 val; val.x = lo * scale; val.y = hi * scale;
            *(float2*)&g_att[(p * NN + i) * NN + j] = val;
        }
    }
}

// ---------------------------------------------------------------------------
// K3: masked softmax over j (group mask from roi_inds).  Warp = one (p,i) row.
// Invalid entries -> exp underflows to exactly 0, so K4 is a dense GEMM.
// ---------------------------------------------------------------------------
__global__ __launch_bounds__(256) void softmax_kernel(const int* __restrict__ roi)
{
    __shared__ int rg[256];
    const int tid = threadIdx.x, l = tid & 31, wp = tid >> 5;
    rg[tid] = roi[tid];
    __syncthreads();
    const int row = blockIdx.x * 8 + wp;
    const int p = row >> 8, i = row & 255;
    const int gi = rg[i];
    float* rowp = &g_att[(p * NN + i) * NN];

    float v[8];
#pragma unroll
    for (int jj = 0; jj < 8; jj++) {
        int j = jj * 32 + l;
        float s = rowp[j];
        v[jj] = (rg[j] == gi) ? s : -1e30f;
    }
    float m = v[0];
#pragma unroll
    for (int jj = 1; jj < 8; jj++) m = fmaxf(m, v[jj]);
#pragma unroll
    for (int off = 16; off; off >>= 1) m = fmaxf(m, __shfl_xor_sync(0xffffffffu, m, off));

    float e[8]; float sum = 0.0f;
#pragma unroll
    for (int jj = 0; jj < 8; jj++) { e[jj] = expf(v[jj] - m); sum += e[jj]; }
#pragma unroll
    for (int off = 16; off; off >>= 1) sum += __shfl_xor_sync(0xffffffffu, sum, off);
    const float inv = 1.0f / sum;
#pragma unroll
    for (int jj = 0; jj < 8; jj++) rowp[jj * 32 + l] = e[jj] * inv;
}

// ---------------------------------------------------------------------------
// K4: virt_p = att_p · V_p.  Block = 64 i-rows × 128 c-cols of one p.
// ---------------------------------------------------------------------------
__global__ __launch_bounds__(256) void virt_kernel()
{
    __shared__ __align__(16) float as_[16 * 64];   // [jj][i]
    __shared__ __align__(16) float vs_[16 * 128];  // [jj][c]
    const int p = blockIdx.y;
    const int ct = blockIdx.x & 3, it = blockIdx.x >> 2;
    const int tid = threadIdx.x, l = tid & 31, wp = tid >> 5;

    ull acc[8][2];
#pragma unroll
    for (int r = 0; r < 8; r++) { acc[r][0] = 0ULL; acc[r][1] = 0ULL; }

    for (int j0 = 0; j0 < NN; j0 += 16) {
        for (int idx = tid; idx < 1024; idx += 256) {
            int i_loc = idx >> 4, jj = idx & 15;
            as_[jj * 64 + i_loc] = g_att[(p * NN + it * 64 + i_loc) * NN + j0 + jj];
        }
        for (int idx = tid; idx < 2048; idx += 256) {
            int jj = idx >> 7, cl = idx & 127;
            vs_[jj * 128 + cl] = g_v[(p * NN + j0 + jj) * CC + ct * 128 + cl];
        }
        __syncthreads();
#pragma unroll
        for (int jj = 0; jj < 16; jj++) {
            ull vA = *(const ull*)&vs_[jj * 128 + 2 * l];
            ull vB = *(const ull*)&vs_[jj * 128 + 64 + 2 * l];
#pragma unroll
            for (int r = 0; r < 8; r++) {
                ull ab = pack2(as_[jj * 64 + wp * 8 + r]);
                acc[r][0] = fma2(ab, vA, acc[r][0]);
                acc[r][1] = fma2(ab, vB, acc[r][1]);
            }
        }
        __syncthreads();
    }
#pragma unroll
    for (int r = 0; r < 8; r++) {
        const int i = it * 64 + wp * 8 + r;
#pragma unroll
        for (int hf = 0; hf < 2; hf++) {
            const int c = ct * 128 + hf * 64 + 2 * l;
            *(ull*)&g_virt[(p * NN + i) * CC + c] = acc[r][hf];
        }
    }
}

// ---------------------------------------------------------------------------
// K5: GroupNorm(num_groups=1) stats per sample n: mean/var over (C,T,H,W).
// ---------------------------------------------------------------------------
__global__ __launch_bounds__(256) void stats_kernel()
{
    __shared__ float r1[256];
    __shared__ float r2[256];
    const int n = blockIdx.x;
    const int tid = threadIdx.x;
    float s = 0.0f, s2 = 0.0f;
    for (int e = tid; e < PP * CC; e += 256) {
        int p = e >> 9, c = e & 511;
        float v = g_virt[(p * NN + n) * CC + c];
        s += v; s2 += v * v;
    }
    r1[tid] = s; r2[tid] = s2;
    __syncthreads();
    for (int off = 128; off; off >>= 1) {
        if (tid < off) { r1[tid] += r1[tid + off]; r2[tid] += r2[tid + off]; }
        __syncthreads();
    }
    if (tid == 0) {
        const float invN = 1.0f / (float)(PP * CC);
        float mu = r1[0] * invN;
        float var = r2[0] * invN - mu * mu;
        g_mu[n] = mu;
        g_rs[n] = rsqrtf(var + 1e-5f);
    }
}

// ---------------------------------------------------------------------------
// K7: out = x + conv1x3x3( relu(GN(virt)), Wc ).
// Normalization + relu fused into the smem tile load (zero halo applied AFTER
// the nonlinearity, matching the reference's conv padding of the activated map).
// ---------------------------------------------------------------------------
__global__ __launch_bounds__(256) void conv_out_kernel(
    const float* __restrict__ x,
    const float* __restrict__ Wc,
    const float* __restrict__ gamma,
    const float* __restrict__ beta,
    float* __restrict__ out)
{
    __shared__ __align__(16) float ws[16 * 9 * 64];   // [ci][s][co] 36.9 KB
    __shared__ __align__(16) float xs[16 * 10 * 10];  // 6.4 KB

    const int co_base = blockIdx.x * 64;
    const int nt = blockIdx.y;
    const int n = nt >> 2, t = nt & 3;
    const int tid = threadIdx.x, l = tid & 31, wp = tid >> 5;
    const float mu = g_mu[n], rs = g_rs[n];

    ull acc[8];
#pragma unroll
    for (int i = 0; i < 8; i++) acc[i] = 0ULL;

    for (int kb = 0; kb < 32; kb++) {
        const int ci0 = kb * 16;
        for (int idx = tid; idx < 9216; idx += 256) {
            int co = idx / 144; int r = idx - co * 144;
            int ci = r / 9;     int s = r - ci * 9;
            ws[(ci * 9 + s) * 64 + co] = Wc[((co_base + co) * CC + ci0 + ci) * 9 + s];
        }
        for (int idx = tid; idx < 1600; idx += 256) {
            int ci = idx / 100; int r = idx - ci * 100;
            int hh = r / 10;    int wwv = r - hh * 10;
            int hs = hh - 1, wsv = wwv - 1;
            float val = 0.0f;
            if ((unsigned)hs < 8u && (unsigned)wsv < 8u) {
                int c = ci0 + ci;
                float raw = g_virt[((t * HWSZ + hs * 8 + wsv) * NN + n) * CC + c];
                float ag = rs * gamma[c];
                val = fmaxf(fmaf(raw, ag, beta[c] - mu * ag), 0.0f);
            }
            xs[idx] = val;
        }
        __syncthreads();
#pragma unroll
        for (int ci = 0; ci < 16; ci++) {
#pragma unroll
            for (int dh = 0; dh < 3; dh++) {
                const float* row = &xs[(ci * 10 + wp + dh) * 10];
                ull xr2[10];
#pragma unroll
                for (int j = 0; j < 10; j++) xr2[j] = pack2(row[j]);
#pragma unroll
                for (int dw = 0; dw < 3; dw++) {
                    ull w2 = *(const ull*)&ws[(ci * 9 + dh * 3 + dw) * 64 + 2 * l];
#pragma unroll
                    for (int i = 0; i < 8; i++)
                        acc[i] = fma2(w2, xr2[i + dw], acc[i]);
                }
            }
        }
        __syncthreads();
    }
    // residual add + store in native [N][C][T][H][W] layout
#pragma unroll
    for (int i = 0; i < 8; i++) {
        float lo, hi;
        unpack2(acc[i], lo, hi);
        const int sp = wp * 8 + i;
        const int a0 = ((n * CC + co_base + 2 * l) * TT + t) * HWSZ + sp;
        const int a1 = a0 + TT * HWSZ;   // next channel
        out[a0] = x[a0] + lo;
        out[a1] = x[a1] + hi;
    }
}

// ---------------------------------------------------------------------------
// Launch
// ---------------------------------------------------------------------------
extern "C" void kernel_launch(void* const* d_in, const int* in_sizes, int n_in,
                              void* d_out, int out_size)
{
    const float* x     = (const float*)d_in[0];
    const int*   roi   = (const int*)d_in[1];
    const float* Wq    = (const float*)d_in[2];
    const float* Wk    = (const float*)d_in[3];
    const float* Wv    = (const float*)d_in[4];
    const float* Wc    = (const float*)d_in[5];
    const float* gamma = (const float*)d_in[6];
    const float* beta  = (const float*)d_in[7];
    float* out = (float*)d_out;

    conv_qkv_kernel<<<dim3(8, 1024), 256>>>(x, Wq, Wk, Wv);
    scores_kernel<<<dim3(8, 256), 256>>>();
    softmax_kernel<<<dim3(8192), 256>>>(roi);
    virt_kernel<<<dim3(16, 256), 256>>>();
    stats_kernel<<<dim3(256), 256>>>();
    conv_out_kernel<<<dim3(8, 1024), 256>>>(x, Wc, gamma, beta, out);
}